// round 13
// baseline (speedup 1.0000x reference)
#include <cuda_runtime.h>
#include <cuda_fp16.h>
#include <cstdint>

#define NROW 4096
#define IND  128
#define OD   64
#define NH   4
#define NC   80          // padded hv cols in gmem: 64 h | col64=1.0 | 65..79=0
#define HS_STRIDE 88     // smem stride (halves)
#define KC   64          // k-chunk (columns m per iteration)
#define RT   128         // row tile per block (8 warps x 16 rows)
#define KSPLIT 4
#define ITER_PER (NROW/KC/KSPLIT)   // 16
#define NW   (NROW/32)   // adj bit words per row = 128

// ---------------- scratch (static device globals; no cudaMalloc) ----------------
__device__ __half   g_hv[NH*NROW*NC];       // 2.6 MB  (h fp16 + ones col + pad)
__device__ __half   g_u[NH*NROW];           // e^t      (PERMUTED within 64-chunks)
__device__ __half   g_v[NH*NROW];           // e^{0.2t} (PERMUTED)
__device__ __half   g_th[NH*NROW];          // t        (PERMUTED)
__device__ __half2  g_E2[NH*NROW];          // (e^{0.8c}, e^{0.8c})
__device__ __half2  g_nc[NH*NROW];          // (-c, -c)
__device__ uint32_t g_adjbits[NROW*NW];     // 2 MB bit-packed adjacency
__device__ float    g_part[KSPLIT*NH*NROW*80]; // 21 MB split-K partials

// ---------------- helpers ----------------
__device__ __forceinline__ uint32_t smem_u32(const void* p) {
    return (uint32_t)__cvta_generic_to_shared(p);
}
__device__ __forceinline__ void ldm_x4_t(uint32_t& r0, uint32_t& r1, uint32_t& r2, uint32_t& r3, uint32_t addr) {
    asm volatile("ldmatrix.sync.aligned.m8n8.x4.trans.shared.b16 {%0,%1,%2,%3}, [%4];"
                 : "=r"(r0), "=r"(r1), "=r"(r2), "=r"(r3) : "r"(addr));
}
__device__ __forceinline__ void ldm_x2_t(uint32_t& r0, uint32_t& r1, uint32_t addr) {
    asm volatile("ldmatrix.sync.aligned.m8n8.x2.trans.shared.b16 {%0,%1}, [%2];"
                 : "=r"(r0), "=r"(r1) : "r"(addr));
}
__device__ __forceinline__ void mma16816(float* c, const uint32_t* a, const uint32_t* b) {
    asm volatile("mma.sync.aligned.m16n8k16.row.col.f32.f16.f16.f32 "
                 "{%0,%1,%2,%3}, {%4,%5,%6,%7}, {%8,%9}, {%0,%1,%2,%3};"
                 : "+f"(c[0]), "+f"(c[1]), "+f"(c[2]), "+f"(c[3])
                 : "r"(a[0]), "r"(a[1]), "r"(a[2]), "r"(a[3]), "r"(b[0]), "r"(b[1]));
}
__device__ __forceinline__ void cp16(void* smem_dst, const void* gmem_src) {
    asm volatile("cp.async.cg.shared.global [%0], [%1], 16;"
                 :: "r"(smem_u32(smem_dst)), "l"(gmem_src));
}
__device__ __forceinline__ void cp_commit() {
    asm volatile("cp.async.commit_group;");
}
__device__ __forceinline__ void cp_wait1() {
    asm volatile("cp.async.wait_group 1;");
}

// P value for one (row, column-pair), with the e^{0.2c} row factor divided out:
//   P = adj ? (t > -c ? e^{0.8c} * e^t : e^{0.2t}) : 0
__device__ __forceinline__ uint32_t pval(__half2 u, __half2 v, __half2 t,
                                         __half2 E, __half2 nc,
                                         uint32_t w, int sh) {
    __half2 pos = __hmul2(u, E);
    uint32_t cm = __hgt2_mask(t, nc);
    uint32_t r = ((*(uint32_t*)&pos) & cm) | ((*(uint32_t*)&v) & ~cm);
    uint32_t al = (uint32_t)((int)(w << (31 - sh)) >> 31);   // bit sh   -> all 32
    uint32_t ah = (uint32_t)((int)(w << (30 - sh)) >> 31);   // bit sh+1 -> all 32
    uint32_t am = __byte_perm(al, ah, 0x7610);               // lo16 from al, hi16 from ah
    return r & am;
}

// ---------------- KA: proj/scores blocks first, then 8-row prefetched adjacency pack ----------------
// blocks [0, 256):       projection tiles (64 rows x head) + per-row score exps
// blocks [256, 256+512): adjacency pack, 8 rows/block, register prefetch across rows
__global__ __launch_bounds__(256) void kA(const float* __restrict__ x,
                                          const float* __restrict__ adj,
                                          const float* __restrict__ W,
                                          const float* __restrict__ a_self,
                                          const float* __restrict__ a_neigh) {
    __shared__ float xs[64][33];   // 8.4 KB
    __shared__ float ws[32][68];   // 8.7 KB
    int bid = blockIdx.x;
    int tid = threadIdx.x;

    if (bid >= 256) {
        // ---- adjacency bit-pack: 8 rows/block, coalesced float4, row prefetch ----
        int row0 = (bid - 256) * 8;
        int wq = tid >> 5, lane = tid & 31;
        int sh4 = (lane & 7) * 4;
        const float4* p4 = (const float4*)adj + (size_t)row0 * (NROW / 4);
        float4 v[4], vn[4];
        #pragma unroll
        for (int j = 0; j < 4; j++) v[j] = p4[(wq * 4 + j) * 32 + lane];
        for (int rr = 0; rr < 8; rr++) {
            if (rr < 7) {
                const float4* pn = (const float4*)adj + (size_t)(row0 + rr + 1) * (NROW / 4);
                #pragma unroll
                for (int j = 0; j < 4; j++) vn[j] = pn[(wq * 4 + j) * 32 + lane];
            }
            int row = row0 + rr;
            #pragma unroll
            for (int j = 0; j < 4; j++) {
                float f = v[j].x + 2.f * v[j].y + 4.f * v[j].z + 8.f * v[j].w;
                uint32_t r = ((uint32_t)(int)f) << sh4;
                r |= __shfl_xor_sync(0xffffffffu, r, 1);
                r |= __shfl_xor_sync(0xffffffffu, r, 2);
                r |= __shfl_xor_sync(0xffffffffu, r, 4);
                if ((lane & 7) == 0)
                    g_adjbits[row * NW + (wq * 4 + j) * 4 + (lane >> 3)] = r;
            }
            #pragma unroll
            for (int j = 0; j < 4; j++) v[j] = vn[j];
        }
        return;
    }

    // ---- projection tile: 64 rows x 64 cols for one head, k-chunks of 32 ----
    int head = bid >> 6;
    int r0 = (bid & 63) * 64;
    int tx = tid & 15, ty = tid >> 4;
    float acc[4][4] = {};
    for (int k0 = 0; k0 < IND; k0 += 32) {
        for (int idx = tid; idx < 64 * 32; idx += 256) {
            int r = idx >> 5, c = idx & 31;
            xs[r][c] = x[(r0 + r) * IND + k0 + c];
        }
        for (int idx = tid; idx < 32 * 64; idx += 256) {
            int r = idx >> 6, c = idx & 63;
            ws[r][c] = W[head * IND * OD + (k0 + r) * OD + c];
        }
        __syncthreads();
        for (int k = 0; k < 32; k++) {
            float4 wv = *(const float4*)&ws[k][tx * 4];
            #pragma unroll
            for (int i = 0; i < 4; i++) {
                float xv = xs[ty + 16 * i][k];
                acc[i][0] += xv * wv.x;
                acc[i][1] += xv * wv.y;
                acc[i][2] += xv * wv.z;
                acc[i][3] += xv * wv.w;
            }
        }
        __syncthreads();
    }
    // hv (fp16) + pad cols
    #pragma unroll
    for (int i = 0; i < 4; i++)
        #pragma unroll
        for (int j = 0; j < 4; j++) {
            int r = r0 + ty + 16 * i, c = tx * 4 + j;
            g_hv[(head * NROW + r) * NC + c] = __float2half(acc[i][j]);
        }
    for (int idx = tid; idx < 64 * 16; idx += 256) {
        int r = idx >> 4, pc = idx & 15;
        g_hv[(head * NROW + r0 + r) * NC + 64 + pc] =
            (pc == 0) ? __float2half(1.0f) : __float2half(0.0f);
    }
    // score dot partials (reuse xs as scratch: 2048 floats; xs has 2112)
    float as[4], an[4];
    #pragma unroll
    for (int j = 0; j < 4; j++) {
        as[j] = __ldg(&a_self[head * OD + tx * 4 + j]);
        an[j] = __ldg(&a_neigh[head * OD + tx * 4 + j]);
    }
    float* sp = &xs[0][0];
    #pragma unroll
    for (int i = 0; i < 4; i++) {
        float ps = 0.f, pn = 0.f;
        #pragma unroll
        for (int j = 0; j < 4; j++) { ps += acc[i][j] * as[j]; pn += acc[i][j] * an[j]; }
        int row = ty + 16 * i;
        sp[row * 16 + tx] = ps;
        sp[1024 + row * 16 + tx] = pn;
    }
    __syncthreads();
    if (tid < 64) {
        float c = 0.f, t = 0.f;
        #pragma unroll
        for (int xq = 0; xq < 16; xq++) {
            c += sp[tid * 16 + xq];
            t += sp[1024 + tid * 16 + xq];
        }
        int i = head * NROW + r0 + tid;
        // u/v/th written PERMUTED within the 64-chunk so k4's per-thread pair
        // (p, p+4) lands adjacent: half2 p -> q = (p&3)*8 + (p>>2)
        int p = tid >> 1, lh = tid & 1;
        int q = ((p & 3) << 3) | (p >> 2);
        int ip = head * NROW + r0 + q * 2 + lh;
        g_u[ip]  = __float2half(expf(t));
        g_v[ip]  = __float2half(expf(0.2f * t));
        g_th[ip] = __float2half(t);
        g_E2[i] = __float2half2_rn(expf(0.8f * c));
        g_nc[i] = __float2half2_rn(-c);
    }
}

// ---------------- K4: split-K(4), RT=128 (8 m-tile warps), N=72, 3-stage cp.async ring ----------------
__global__ __launch_bounds__(256, 3) void k4_main() {
    __shared__ __align__(16) __half  Hs[3][KC][HS_STRIDE];
    __shared__ __align__(16) __half2 U2s[3][KC/2];
    __shared__ __align__(16) __half2 V2s[3][KC/2];
    __shared__ __align__(16) __half2 T2s[3][KC/2];

    int head = blockIdx.y;
    int n0 = blockIdx.x * RT;
    int z = blockIdx.z;                  // k-split index
    int kb0 = z * ITER_PER;
    int tid = threadIdx.x;
    int lane = tid & 31, wid = tid >> 5; // wid = m-tile 0..7
    int g = lane >> 2, tc = lane & 3;

    int ra = n0 + wid * 16 + g;
    int rb = ra + 8;
    int ia = head * NROW + ra, ib = head * NROW + rb;
    __half2 Ea = g_E2[ia], nca = g_nc[ia];
    __half2 Eb = g_E2[ib], ncb = g_nc[ib];
    const uint2* adjA = (const uint2*)&g_adjbits[ra * NW];  // [kb] -> 64 cols
    const uint2* adjB = (const uint2*)&g_adjbits[rb * NW];

    float acc[9][4];
    #pragma unroll
    for (int b = 0; b < 9; b++)
        #pragma unroll
        for (int c = 0; c < 4; c++) acc[b][c] = 0.0f;

    const float4* hv4 = (const float4*)&g_hv[head * NROW * NC];
    const __half* gu = g_u + head * NROW;
    const __half* gv = g_v + head * NROW;
    const __half* gt = g_th + head * NROW;

    int kbEnd = kb0 + ITER_PER;
    auto issue = [&](int kbg, int s) {
        if (kbg < kbEnd) {
            int m0 = kbg * KC;
            #pragma unroll
            for (int i = 0; i < 3; i++) {
                int idx = tid + i * 256;
                if (idx < 64 * 9) {
                    int r = idx / 9, cg = idx - r * 9;
                    cp16(((char*)&Hs[s][r][0]) + cg * 16, (const char*)(hv4 + (m0 + r) * 10 + cg));
                }
            }
            if (tid < 24) {
                int a = tid >> 3, i = tid & 7;
                const __half* src = (a == 0 ? gu : (a == 1 ? gv : gt)) + m0 + i * 8;
                __half2* dst = (a == 0 ? &U2s[s][0] : (a == 1 ? &V2s[s][0] : &T2s[s][0])) + i * 4;
                cp16(dst, src);
            }
        }
        cp_commit();   // commit unconditionally to keep group accounting aligned
    };

    issue(kb0, 0);
    issue(kb0 + 1, 1);
    uint2 awa = __ldg(&adjA[kb0]);
    uint2 awb = __ldg(&adjB[kb0]);

    for (int k2 = 0; k2 < ITER_PER; k2++) {
        int s = k2 % 3;
        cp_wait1();            // stage k2 arrived (stage k2+1 may still be in flight)
        __syncthreads();       // all warps past compute of k2-1 -> stage (k2+2)%3 free
        issue(kb0 + k2 + 2, (k2 + 2) % 3);
        uint2 nwa = make_uint2(0u, 0u), nwb = make_uint2(0u, 0u);
        if (k2 + 1 < ITER_PER) {
            nwa = __ldg(&adjA[kb0 + k2 + 1]);
            nwb = __ldg(&adjB[kb0 + k2 + 1]);
        }

        const char* HsB = (const char*)&Hs[s][0][0];
        int qb = tc * 8;      // permuted base for this thread's column pairs
        #pragma unroll
        for (int kk = 0; kk < 4; kk++) {
            int p0 = kk * 8 + tc;            // logical pair index (for adjacency bits)
            int p1 = p0 + 4;
            uint32_t wa = (kk < 2) ? awa.x : awa.y;
            uint32_t wb = (kk < 2) ? awb.x : awb.y;
            int sh0 = (2 * p0) & 31;
            int sh1 = (2 * p1) & 31;

            // permuted smem: pairs (p0, p1) adjacent -> single 64-bit LDS each
            float2 uf = *(const float2*)&U2s[s][qb + 2 * kk];
            float2 vf = *(const float2*)&V2s[s][qb + 2 * kk];
            float2 tf = *(const float2*)&T2s[s][qb + 2 * kk];
            __half2 u0 = ((const __half2*)&uf)[0], u1 = ((const __half2*)&uf)[1];
            __half2 v0 = ((const __half2*)&vf)[0], v1 = ((const __half2*)&vf)[1];
            __half2 t0 = ((const __half2*)&tf)[0], t1 = ((const __half2*)&tf)[1];

            uint32_t a[4];
            a[0] = pval(u0, v0, t0, Ea, nca, wa, sh0);
            a[1] = pval(u0, v0, t0, Eb, ncb, wb, sh0);
            a[2] = pval(u1, v1, t1, Ea, nca, wa, sh1);
            a[3] = pval(u1, v1, t1, Eb, ncb, wb, sh1);

            const char* rowK = HsB + (kk * 16 + (lane & 15)) * (HS_STRIDE * 2);
            const char* rowB = rowK + ((lane >> 4) * 8) * 2;
            // cols 0..63: 4 x4 transposed loads, mma immediately
            #pragma unroll
            for (int gg = 0; gg < 4; gg++) {
                uint32_t b0[2], b1[2];
                ldm_x4_t(b0[0], b0[1], b1[0], b1[1],
                         smem_u32(rowB + (gg * 16) * 2));
                mma16816(&acc[2 * gg][0], a, b0);
                mma16816(&acc[2 * gg + 1][0], a, b1);
            }
            // cols 64..71 (denominator col 64 + zero pad): one x2 load
            {
                uint32_t b2[2];
                ldm_x2_t(b2[0], b2[1], smem_u32(rowK + 64 * 2));
                mma16816(&acc[8][0], a, b2);
            }
        }
        awa = nwa;
        awb = nwb;
    }

    // store unnormalized partials (cols 0..71 incl. denominator col 64)
    float* pb = g_part + ((size_t)(z * NH + head) * NROW) * 80;
    int row0 = n0 + wid * 16 + g;
    #pragma unroll
    for (int nt = 0; nt < 9; nt++) {
        int col = nt * 8 + 2 * tc;
        *(float2*)&pb[(size_t)row0 * 80 + col] = make_float2(acc[nt][0], acc[nt][1]);
        *(float2*)&pb[(size_t)(row0 + 8) * 80 + col] = make_float2(acc[nt][2], acc[nt][3]);
    }
}

// ---------------- K5: combine split-K partials + normalize + write out ----------------
__global__ __launch_bounds__(256) void k5_combine(float* __restrict__ out) {
    int head = blockIdx.y;
    int r = blockIdx.x * 64 + (threadIdx.x >> 2);
    int q = threadIdx.x & 3;
    const float* p0 = g_part + ((size_t)(0 * NH + head) * NROW + r) * 80;
    const float* p1 = g_part + ((size_t)(1 * NH + head) * NROW + r) * 80;
    const float* p2 = g_part + ((size_t)(2 * NH + head) * NROW + r) * 80;
    const float* p3 = g_part + ((size_t)(3 * NH + head) * NROW + r) * 80;
    float inv = 1.0f / (p0[64] + p1[64] + p2[64] + p3[64]);
    #pragma unroll
    for (int j = 0; j < 4; j++) {
        float4 a = *(const float4*)&p0[q * 16 + j * 4];
        float4 b = *(const float4*)&p1[q * 16 + j * 4];
        float4 c = *(const float4*)&p2[q * 16 + j * 4];
        float4 d = *(const float4*)&p3[q * 16 + j * 4];
        float4 o;
        o.x = (a.x + b.x + c.x + d.x) * inv;
        o.y = (a.y + b.y + c.y + d.y) * inv;
        o.z = (a.z + b.z + c.z + d.z) * inv;
        o.w = (a.w + b.w + c.w + d.w) * inv;
        *(float4*)&out[(size_t)r * (NH * OD) + head * OD + q * 16 + j * 4] = o;
    }
}

// ---------------- launch ----------------
extern "C" void kernel_launch(void* const* d_in, const int* in_sizes, int n_in,
                              void* d_out, int out_size) {
    const float* x       = (const float*)d_in[0];
    const float* adj     = (const float*)d_in[1];
    const float* W       = (const float*)d_in[2];
    const float* a_self  = (const float*)d_in[3];
    const float* a_neigh = (const float*)d_in[4];
    float* out = (float*)d_out;

    kA        <<<256 + 512, 256>>>(x, adj, W, a_self, a_neigh);
    k4_main   <<<dim3(NROW / RT, NH, KSPLIT), 256>>>();
    k5_combine<<<dim3(NROW / 64, NH), 256>>>(out);
}

// round 14
// speedup vs baseline: 1.0238x; 1.0238x over previous
#include <cuda_runtime.h>
#include <cuda_fp16.h>
#include <cstdint>

#define NROW 4096
#define IND  128
#define OD   64
#define NH   4
#define NC   80          // padded hv cols in gmem: 64 h | col64=1.0 | 65..79=0
#define HS_STRIDE 88     // smem stride (halves)
#define KC   64          // k-chunk (columns m per iteration)
#define RT   64          // row tile per block
#define KSPLIT 4
#define ITER_PER (NROW/KC/KSPLIT)   // 16
#define NW   (NROW/32)   // adj bit words per row = 128

// ---------------- scratch (static device globals; no cudaMalloc) ----------------
__device__ __half   g_hv[NH*NROW*NC];       // 2.6 MB  (h fp16 + ones col + pad)
__device__ __half   g_u[NH*NROW];           // e^t      (PERMUTED within 64-chunks)
__device__ __half   g_v[NH*NROW];           // e^{0.2t} (PERMUTED)
__device__ __half   g_th[NH*NROW];          // t        (PERMUTED)
__device__ __half2  g_E2[NH*NROW];          // (e^{0.8c}, e^{0.8c})
__device__ __half2  g_nc[NH*NROW];          // (-c, -c)
__device__ uint32_t g_adjbits[NROW*NW];     // 2 MB bit-packed adjacency
__device__ float    g_part[KSPLIT*NH*NROW*80]; // 21 MB split-K partials

// ---------------- helpers ----------------
__device__ __forceinline__ uint32_t smem_u32(const void* p) {
    return (uint32_t)__cvta_generic_to_shared(p);
}
__device__ __forceinline__ void ldm_x4_t(uint32_t& r0, uint32_t& r1, uint32_t& r2, uint32_t& r3, uint32_t addr) {
    asm volatile("ldmatrix.sync.aligned.m8n8.x4.trans.shared.b16 {%0,%1,%2,%3}, [%4];"
                 : "=r"(r0), "=r"(r1), "=r"(r2), "=r"(r3) : "r"(addr));
}
__device__ __forceinline__ void ldm_x2_t(uint32_t& r0, uint32_t& r1, uint32_t addr) {
    asm volatile("ldmatrix.sync.aligned.m8n8.x2.trans.shared.b16 {%0,%1}, [%2];"
                 : "=r"(r0), "=r"(r1) : "r"(addr));
}
__device__ __forceinline__ void mma16816(float* c, const uint32_t* a, const uint32_t* b) {
    asm volatile("mma.sync.aligned.m16n8k16.row.col.f32.f16.f16.f32 "
                 "{%0,%1,%2,%3}, {%4,%5,%6,%7}, {%8,%9}, {%0,%1,%2,%3};"
                 : "+f"(c[0]), "+f"(c[1]), "+f"(c[2]), "+f"(c[3])
                 : "r"(a[0]), "r"(a[1]), "r"(a[2]), "r"(a[3]), "r"(b[0]), "r"(b[1]));
}
__device__ __forceinline__ void cp16(void* smem_dst, const void* gmem_src) {
    asm volatile("cp.async.cg.shared.global [%0], [%1], 16;"
                 :: "r"(smem_u32(smem_dst)), "l"(gmem_src));
}
__device__ __forceinline__ void cp_commit() {
    asm volatile("cp.async.commit_group;");
}
__device__ __forceinline__ void cp_wait1() {
    asm volatile("cp.async.wait_group 1;");
}

// P value for one (row, column-pair), with the e^{0.2c} row factor divided out:
//   P = adj ? (t > -c ? e^{0.8c} * e^t : e^{0.2t}) : 0
__device__ __forceinline__ uint32_t pval(__half2 u, __half2 v, __half2 t,
                                         __half2 E, __half2 nc,
                                         uint32_t w, int sh) {
    __half2 pos = __hmul2(u, E);
    uint32_t cm = __hgt2_mask(t, nc);
    uint32_t r = ((*(uint32_t*)&pos) & cm) | ((*(uint32_t*)&v) & ~cm);
    uint32_t al = (uint32_t)((int)(w << (31 - sh)) >> 31);   // bit sh   -> all 32
    uint32_t ah = (uint32_t)((int)(w << (30 - sh)) >> 31);   // bit sh+1 -> all 32
    uint32_t am = __byte_perm(al, ah, 0x7610);               // lo16 from al, hi16 from ah
    return r & am;
}

// ---------------- KA: proj/scores blocks first, then coalesced adjacency pack ----------------
// blocks [0, 256):           projection tiles (64 rows x head) + per-row score exps
// blocks [256, 256+4096):    adjacency pack, 1 row/block, coalesced float4 + shfl-or
__global__ __launch_bounds__(256) void kA(const float* __restrict__ x,
                                          const float* __restrict__ adj,
                                          const float* __restrict__ W,
                                          const float* __restrict__ a_self,
                                          const float* __restrict__ a_neigh) {
    __shared__ float xs[64][33];   // 8.4 KB
    __shared__ float ws[32][68];   // 8.7 KB
    int bid = blockIdx.x;
    int tid = threadIdx.x;

    if (bid >= 256) {
        // ---- adjacency bit-pack: 1 row/block; coalesced loads, nibble shfl-or ----
        int row = bid - 256;
        int wq = tid >> 5, lane = tid & 31;   // warp wq handles windows wq*4..wq*4+3
        const float4* p4 = (const float4*)(adj + (size_t)row * NROW);
        float4 v[4];
        #pragma unroll
        for (int j = 0; j < 4; j++)
            v[j] = p4[(wq * 4 + j) * 32 + lane];   // lanes contiguous: 4 lines/instr
        int sh4 = (lane & 7) * 4;
        #pragma unroll
        for (int j = 0; j < 4; j++) {
            float f = v[j].x + 2.f * v[j].y + 4.f * v[j].z + 8.f * v[j].w;
            uint32_t r = ((uint32_t)(int)f) << sh4;
            r |= __shfl_xor_sync(0xffffffffu, r, 1);
            r |= __shfl_xor_sync(0xffffffffu, r, 2);
            r |= __shfl_xor_sync(0xffffffffu, r, 4);
            if ((lane & 7) == 0)
                g_adjbits[row * NW + (wq * 4 + j) * 4 + (lane >> 3)] = r;
        }
        return;
    }

    // ---- projection tile: 64 rows x 64 cols for one head, k-chunks of 32 ----
    int head = bid >> 6;
    int r0 = (bid & 63) * 64;
    int tx = tid & 15, ty = tid >> 4;
    float acc[4][4] = {};
    for (int k0 = 0; k0 < IND; k0 += 32) {
        for (int idx = tid; idx < 64 * 32; idx += 256) {
            int r = idx >> 5, c = idx & 31;
            xs[r][c] = x[(r0 + r) * IND + k0 + c];
        }
        for (int idx = tid; idx < 32 * 64; idx += 256) {
            int r = idx >> 6, c = idx & 63;
            ws[r][c] = W[head * IND * OD + (k0 + r) * OD + c];
        }
        __syncthreads();
        for (int k = 0; k < 32; k++) {
            float4 wv = *(const float4*)&ws[k][tx * 4];
            #pragma unroll
            for (int i = 0; i < 4; i++) {
                float xv = xs[ty + 16 * i][k];
                acc[i][0] += xv * wv.x;
                acc[i][1] += xv * wv.y;
                acc[i][2] += xv * wv.z;
                acc[i][3] += xv * wv.w;
            }
        }
        __syncthreads();
    }
    // hv (fp16) + pad cols
    #pragma unroll
    for (int i = 0; i < 4; i++)
        #pragma unroll
        for (int j = 0; j < 4; j++) {
            int r = r0 + ty + 16 * i, c = tx * 4 + j;
            g_hv[(head * NROW + r) * NC + c] = __float2half(acc[i][j]);
        }
    for (int idx = tid; idx < 64 * 16; idx += 256) {
        int r = idx >> 4, pc = idx & 15;
        g_hv[(head * NROW + r0 + r) * NC + 64 + pc] =
            (pc == 0) ? __float2half(1.0f) : __float2half(0.0f);
    }
    // score dot partials (reuse xs as scratch: 2048 floats; xs has 2112)
    float as[4], an[4];
    #pragma unroll
    for (int j = 0; j < 4; j++) {
        as[j] = __ldg(&a_self[head * OD + tx * 4 + j]);
        an[j] = __ldg(&a_neigh[head * OD + tx * 4 + j]);
    }
    float* sp = &xs[0][0];
    #pragma unroll
    for (int i = 0; i < 4; i++) {
        float ps = 0.f, pn = 0.f;
        #pragma unroll
        for (int j = 0; j < 4; j++) { ps += acc[i][j] * as[j]; pn += acc[i][j] * an[j]; }
        int row = ty + 16 * i;
        sp[row * 16 + tx] = ps;
        sp[1024 + row * 16 + tx] = pn;
    }
    __syncthreads();
    if (tid < 64) {
        float c = 0.f, t = 0.f;
        #pragma unroll
        for (int xq = 0; xq < 16; xq++) {
            c += sp[tid * 16 + xq];
            t += sp[1024 + tid * 16 + xq];
        }
        int i = head * NROW + r0 + tid;
        // u/v/th written PERMUTED within the 64-chunk so k4's per-thread pair
        // (p, p+4) lands adjacent: half2 p -> q = (p&3)*8 + (p>>2)
        int p = tid >> 1, lh = tid & 1;
        int q = ((p & 3) << 3) | (p >> 2);
        int ip = head * NROW + r0 + q * 2 + lh;
        g_u[ip]  = __float2half(expf(t));
        g_v[ip]  = __float2half(expf(0.2f * t));
        g_th[ip] = __float2half(t);
        g_E2[i] = __float2half2_rn(expf(0.8f * c));
        g_nc[i] = __float2half2_rn(-c);
    }
}

// ---------------- K4: split-K(4), 1 warp per 16-row m-tile, N=72, 3-stage cp.async ring ----------------
__global__ __launch_bounds__(128, 6) void k4_main() {
    __shared__ __align__(16) __half  Hs[3][KC][HS_STRIDE];
    __shared__ __align__(16) __half2 U2s[3][KC/2];
    __shared__ __align__(16) __half2 V2s[3][KC/2];
    __shared__ __align__(16) __half2 T2s[3][KC/2];

    int head = blockIdx.y;
    int n0 = blockIdx.x * RT;
    int z = blockIdx.z;                  // k-split index
    int kb0 = z * ITER_PER;
    int tid = threadIdx.x;
    int lane = tid & 31, wid = tid >> 5; // wid = m-tile 0..3
    int g = lane >> 2, tc = lane & 3;

    int ra = n0 + wid * 16 + g;
    int rb = ra + 8;
    int ia = head * NROW + ra, ib = head * NROW + rb;
    __half2 Ea = g_E2[ia], nca = g_nc[ia];
    __half2 Eb = g_E2[ib], ncb = g_nc[ib];
    const uint2* adjA = (const uint2*)&g_adjbits[ra * NW];  // [kb] -> 64 cols
    const uint2* adjB = (const uint2*)&g_adjbits[rb * NW];

    float acc[9][4];
    #pragma unroll
    for (int b = 0; b < 9; b++)
        #pragma unroll
        for (int c = 0; c < 4; c++) acc[b][c] = 0.0f;

    const float4* hv4 = (const float4*)&g_hv[head * NROW * NC];
    const __half* gu = g_u + head * NROW;
    const __half* gv = g_v + head * NROW;
    const __half* gt = g_th + head * NROW;

    int kbEnd = kb0 + ITER_PER;
    auto issue = [&](int kbg, int s) {
        if (kbg < kbEnd) {
            int m0 = kbg * KC;
            #pragma unroll
            for (int i = 0; i < 5; i++) {
                int idx = tid + i * 128;
                if (idx < 64 * 9) {
                    int r = idx / 9, cg = idx - r * 9;
                    cp16(((char*)&Hs[s][r][0]) + cg * 16, (const char*)(hv4 + (m0 + r) * 10 + cg));
                }
            }
            if (tid < 24) {
                int a = tid >> 3, i = tid & 7;
                const __half* src = (a == 0 ? gu : (a == 1 ? gv : gt)) + m0 + i * 8;
                __half2* dst = (a == 0 ? &U2s[s][0] : (a == 1 ? &V2s[s][0] : &T2s[s][0])) + i * 4;
                cp16(dst, src);
            }
        }
        cp_commit();   // commit unconditionally to keep group accounting aligned
    };

    issue(kb0, 0);
    issue(kb0 + 1, 1);
    uint2 awa = __ldg(&adjA[kb0]);
    uint2 awb = __ldg(&adjB[kb0]);

    for (int k2 = 0; k2 < ITER_PER; k2++) {
        int s = k2 % 3;
        cp_wait1();            // stage k2 arrived (stage k2+1 may still be in flight)
        __syncthreads();       // all warps past compute of k2-1 -> stage (k2+2)%3 free
        issue(kb0 + k2 + 2, (k2 + 2) % 3);
        uint2 nwa = make_uint2(0u, 0u), nwb = make_uint2(0u, 0u);
        if (k2 + 1 < ITER_PER) {
            nwa = __ldg(&adjA[kb0 + k2 + 1]);
            nwb = __ldg(&adjB[kb0 + k2 + 1]);
        }

        const char* HsB = (const char*)&Hs[s][0][0];
        int qb = tc * 8;      // permuted base for this thread's column pairs
        #pragma unroll
        for (int kk = 0; kk < 4; kk++) {
            int p0 = kk * 8 + tc;            // logical pair index (for adjacency bits)
            int p1 = p0 + 4;
            uint32_t wa = (kk < 2) ? awa.x : awa.y;
            uint32_t wb = (kk < 2) ? awb.x : awb.y;
            int sh0 = (2 * p0) & 31;
            int sh1 = (2 * p1) & 31;

            // permuted smem: pairs (p0, p1) adjacent -> single 64-bit LDS each
            float2 uf = *(const float2*)&U2s[s][qb + 2 * kk];
            float2 vf = *(const float2*)&V2s[s][qb + 2 * kk];
            float2 tf = *(const float2*)&T2s[s][qb + 2 * kk];
            __half2 u0 = ((const __half2*)&uf)[0], u1 = ((const __half2*)&uf)[1];
            __half2 v0 = ((const __half2*)&vf)[0], v1 = ((const __half2*)&vf)[1];
            __half2 t0 = ((const __half2*)&tf)[0], t1 = ((const __half2*)&tf)[1];

            uint32_t a[4];
            a[0] = pval(u0, v0, t0, Ea, nca, wa, sh0);
            a[1] = pval(u0, v0, t0, Eb, ncb, wb, sh0);
            a[2] = pval(u1, v1, t1, Ea, nca, wa, sh1);
            a[3] = pval(u1, v1, t1, Eb, ncb, wb, sh1);

            const char* rowK = HsB + (kk * 16 + (lane & 15)) * (HS_STRIDE * 2);
            const char* rowB = rowK + ((lane >> 4) * 8) * 2;
            // cols 0..63: 4 x4 transposed loads, mma immediately
            #pragma unroll
            for (int gg = 0; gg < 4; gg++) {
                uint32_t b0[2], b1[2];
                ldm_x4_t(b0[0], b0[1], b1[0], b1[1],
                         smem_u32(rowB + (gg * 16) * 2));
                mma16816(&acc[2 * gg][0], a, b0);
                mma16816(&acc[2 * gg + 1][0], a, b1);
            }
            // cols 64..71 (denominator col 64 + zero pad): one x2 load
            {
                uint32_t b2[2];
                ldm_x2_t(b2[0], b2[1], smem_u32(rowK + 64 * 2));
                mma16816(&acc[8][0], a, b2);
            }
        }
        awa = nwa;
        awb = nwb;
    }

    // store unnormalized partials (cols 0..71 incl. denominator col 64)
    float* pb = g_part + ((size_t)(z * NH + head) * NROW) * 80;
    int row0 = n0 + wid * 16 + g;
    #pragma unroll
    for (int nt = 0; nt < 9; nt++) {
        int col = nt * 8 + 2 * tc;
        *(float2*)&pb[(size_t)row0 * 80 + col] = make_float2(acc[nt][0], acc[nt][1]);
        *(float2*)&pb[(size_t)(row0 + 8) * 80 + col] = make_float2(acc[nt][2], acc[nt][3]);
    }
}

// ---------------- K5: combine split-K partials + normalize + write out ----------------
__global__ __launch_bounds__(256) void k5_combine(float* __restrict__ out) {
    int head = blockIdx.y;
    int r = blockIdx.x * 64 + (threadIdx.x >> 2);
    int q = threadIdx.x & 3;
    const float* p0 = g_part + ((size_t)(0 * NH + head) * NROW + r) * 80;
    const float* p1 = g_part + ((size_t)(1 * NH + head) * NROW + r) * 80;
    const float* p2 = g_part + ((size_t)(2 * NH + head) * NROW + r) * 80;
    const float* p3 = g_part + ((size_t)(3 * NH + head) * NROW + r) * 80;
    float inv = 1.0f / (p0[64] + p1[64] + p2[64] + p3[64]);
    #pragma unroll
    for (int j = 0; j < 4; j++) {
        float4 a = *(const float4*)&p0[q * 16 + j * 4];
        float4 b = *(const float4*)&p1[q * 16 + j * 4];
        float4 c = *(const float4*)&p2[q * 16 + j * 4];
        float4 d = *(const float4*)&p3[q * 16 + j * 4];
        float4 o;
        o.x = (a.x + b.x + c.x + d.x) * inv;
        o.y = (a.y + b.y + c.y + d.y) * inv;
        o.z = (a.z + b.z + c.z + d.z) * inv;
        o.w = (a.w + b.w + c.w + d.w) * inv;
        *(float4*)&out[(size_t)r * (NH * OD) + head * OD + q * 16 + j * 4] = o;
    }
}

// ---------------- launch ----------------
extern "C" void kernel_launch(void* const* d_in, const int* in_sizes, int n_in,
                              void* d_out, int out_size) {
    const float* x       = (const float*)d_in[0];
    const float* adj     = (const float*)d_in[1];
    const float* W       = (const float*)d_in[2];
    const float* a_self  = (const float*)d_in[3];
    const float* a_neigh = (const float*)d_in[4];
    float* out = (float*)d_out;

    kA        <<<256 + NROW, 256>>>(x, adj, W, a_self, a_neigh);
    k4_main   <<<dim3(NROW / RT, NH, KSPLIT), 128>>>();
    k5_combine<<<dim3(NROW / 64, NH), 256>>>(out);
}

// round 15
// speedup vs baseline: 1.1021x; 1.0765x over previous
#include <cuda_runtime.h>
#include <cuda_fp16.h>
#include <cstdint>

#define NROW 4096
#define IND  128
#define OD   64
#define NH   4
#define NC   80          // padded hv cols in gmem: 64 h | col64=1.0 | 65..79=0
#define HS_STRIDE 88     // smem stride (halves)
#define KC   64          // k-chunk (columns m per iteration)
#define RT   64          // row tile per block
#define KSPLIT 4
#define ITER_PER (NROW/KC/KSPLIT)   // 16
#define NW   (NROW/32)   // adj bit words per row = 128

// ---------------- scratch (static device globals; no cudaMalloc) ----------------
__device__ __half   g_hv[NH*NROW*NC];       // 2.6 MB  (h fp16 + ones col + pad)
__device__ __half   g_u[NH*NROW];           // e^t      (PERMUTED within 64-chunks)
__device__ __half   g_v[NH*NROW];           // e^{0.2t} (PERMUTED)
__device__ __half   g_th[NH*NROW];          // t        (PERMUTED)
__device__ __half2  g_E2[NH*NROW];          // (e^{0.8c}, e^{0.8c})
__device__ __half2  g_nc[NH*NROW];          // (-c, -c)
__device__ uint32_t g_adjbits[NROW*NW];     // 2 MB bit-packed adjacency
__device__ float    g_part[KSPLIT*NH*NROW*80]; // 21 MB split-K partials

// ---------------- helpers ----------------
__device__ __forceinline__ uint32_t smem_u32(const void* p) {
    return (uint32_t)__cvta_generic_to_shared(p);
}
__device__ __forceinline__ void ldm_x4_t(uint32_t& r0, uint32_t& r1, uint32_t& r2, uint32_t& r3, uint32_t addr) {
    asm volatile("ldmatrix.sync.aligned.m8n8.x4.trans.shared.b16 {%0,%1,%2,%3}, [%4];"
                 : "=r"(r0), "=r"(r1), "=r"(r2), "=r"(r3) : "r"(addr));
}
__device__ __forceinline__ void ldm_x2_t(uint32_t& r0, uint32_t& r1, uint32_t addr) {
    asm volatile("ldmatrix.sync.aligned.m8n8.x2.trans.shared.b16 {%0,%1}, [%2];"
                 : "=r"(r0), "=r"(r1) : "r"(addr));
}
__device__ __forceinline__ void mma16816(float* c, const uint32_t* a, const uint32_t* b) {
    asm volatile("mma.sync.aligned.m16n8k16.row.col.f32.f16.f16.f32 "
                 "{%0,%1,%2,%3}, {%4,%5,%6,%7}, {%8,%9}, {%0,%1,%2,%3};"
                 : "+f"(c[0]), "+f"(c[1]), "+f"(c[2]), "+f"(c[3])
                 : "r"(a[0]), "r"(a[1]), "r"(a[2]), "r"(a[3]), "r"(b[0]), "r"(b[1]));
}
__device__ __forceinline__ void cp16(void* smem_dst, const void* gmem_src) {
    asm volatile("cp.async.cg.shared.global [%0], [%1], 16;"
                 :: "r"(smem_u32(smem_dst)), "l"(gmem_src));
}
__device__ __forceinline__ void cp_commit() {
    asm volatile("cp.async.commit_group;");
}
__device__ __forceinline__ void cp_wait1() {
    asm volatile("cp.async.wait_group 1;");
}

// P value for one (row, column-pair), with the e^{0.2c} row factor divided out:
//   P = adj ? (t > -c ? e^{0.8c} * e^t : e^{0.2t}) : 0
__device__ __forceinline__ uint32_t pval(__half2 u, __half2 v, __half2 t,
                                         __half2 E, __half2 nc,
                                         uint32_t w, int sh) {
    __half2 pos = __hmul2(u, E);
    uint32_t cm = __hgt2_mask(t, nc);
    uint32_t r = ((*(uint32_t*)&pos) & cm) | ((*(uint32_t*)&v) & ~cm);
    uint32_t al = (uint32_t)((int)(w << (31 - sh)) >> 31);   // bit sh   -> all 32
    uint32_t ah = (uint32_t)((int)(w << (30 - sh)) >> 31);   // bit sh+1 -> all 32
    uint32_t am = __byte_perm(al, ah, 0x7610);               // lo16 from al, hi16 from ah
    return r & am;
}

// ---------------- KA: proj/scores blocks first, then coalesced adjacency pack ----------------
// blocks [0, 256):           projection tiles (64 rows x head) + per-row score exps
// blocks [256, 256+4096):    adjacency pack, 1 row/block, coalesced float4 + shfl-or
__global__ __launch_bounds__(256) void kA(const float* __restrict__ x,
                                          const float* __restrict__ adj,
                                          const float* __restrict__ W,
                                          const float* __restrict__ a_self,
                                          const float* __restrict__ a_neigh) {
    __shared__ float xs[64][33];   // 8.4 KB
    __shared__ float ws[32][68];   // 8.7 KB
    int bid = blockIdx.x;
    int tid = threadIdx.x;

    if (bid >= 256) {
        // ---- adjacency bit-pack: 1 row/block; streaming coalesced loads, nibble shfl-or ----
        int row = bid - 256;
        int wq = tid >> 5, lane = tid & 31;   // warp wq handles windows wq*4..wq*4+3
        const float4* p4 = (const float4*)(adj + (size_t)row * NROW);
        float4 v[4];
        #pragma unroll
        for (int j = 0; j < 4; j++)
            v[j] = __ldcs(&p4[(wq * 4 + j) * 32 + lane]);   // evict-first: read-once stream
        int sh4 = (lane & 7) * 4;
        #pragma unroll
        for (int j = 0; j < 4; j++) {
            float f = v[j].x + 2.f * v[j].y + 4.f * v[j].z + 8.f * v[j].w;
            uint32_t r = ((uint32_t)(int)f) << sh4;
            r |= __shfl_xor_sync(0xffffffffu, r, 1);
            r |= __shfl_xor_sync(0xffffffffu, r, 2);
            r |= __shfl_xor_sync(0xffffffffu, r, 4);
            if ((lane & 7) == 0)
                g_adjbits[row * NW + (wq * 4 + j) * 4 + (lane >> 3)] = r;
        }
        return;
    }

    // ---- projection tile: 64 rows x 64 cols for one head, k-chunks of 32 ----
    int head = bid >> 6;
    int r0 = (bid & 63) * 64;
    int tx = tid & 15, ty = tid >> 4;
    float acc[4][4] = {};
    for (int k0 = 0; k0 < IND; k0 += 32) {
        for (int idx = tid; idx < 64 * 32; idx += 256) {
            int r = idx >> 5, c = idx & 31;
            xs[r][c] = x[(r0 + r) * IND + k0 + c];
        }
        for (int idx = tid; idx < 32 * 64; idx += 256) {
            int r = idx >> 6, c = idx & 63;
            ws[r][c] = W[head * IND * OD + (k0 + r) * OD + c];
        }
        __syncthreads();
        for (int k = 0; k < 32; k++) {
            float4 wv = *(const float4*)&ws[k][tx * 4];
            #pragma unroll
            for (int i = 0; i < 4; i++) {
                float xv = xs[ty + 16 * i][k];
                acc[i][0] += xv * wv.x;
                acc[i][1] += xv * wv.y;
                acc[i][2] += xv * wv.z;
                acc[i][3] += xv * wv.w;
            }
        }
        __syncthreads();
    }
    // hv (fp16) + pad cols
    #pragma unroll
    for (int i = 0; i < 4; i++)
        #pragma unroll
        for (int j = 0; j < 4; j++) {
            int r = r0 + ty + 16 * i, c = tx * 4 + j;
            g_hv[(head * NROW + r) * NC + c] = __float2half(acc[i][j]);
        }
    for (int idx = tid; idx < 64 * 16; idx += 256) {
        int r = idx >> 4, pc = idx & 15;
        g_hv[(head * NROW + r0 + r) * NC + 64 + pc] =
            (pc == 0) ? __float2half(1.0f) : __float2half(0.0f);
    }
    // score dot partials (reuse xs as scratch: 2048 floats; xs has 2112)
    float as[4], an[4];
    #pragma unroll
    for (int j = 0; j < 4; j++) {
        as[j] = __ldg(&a_self[head * OD + tx * 4 + j]);
        an[j] = __ldg(&a_neigh[head * OD + tx * 4 + j]);
    }
    float* sp = &xs[0][0];
    #pragma unroll
    for (int i = 0; i < 4; i++) {
        float ps = 0.f, pn = 0.f;
        #pragma unroll
        for (int j = 0; j < 4; j++) { ps += acc[i][j] * as[j]; pn += acc[i][j] * an[j]; }
        int row = ty + 16 * i;
        sp[row * 16 + tx] = ps;
        sp[1024 + row * 16 + tx] = pn;
    }
    __syncthreads();
    if (tid < 64) {
        float c = 0.f, t = 0.f;
        #pragma unroll
        for (int xq = 0; xq < 16; xq++) {
            c += sp[tid * 16 + xq];
            t += sp[1024 + tid * 16 + xq];
        }
        int i = head * NROW + r0 + tid;
        // u/v/th written PERMUTED within the 64-chunk so k4's per-thread pair
        // (p, p+4) lands adjacent: half2 p -> q = (p&3)*8 + (p>>2)
        int p = tid >> 1, lh = tid & 1;
        int q = ((p & 3) << 3) | (p >> 2);
        int ip = head * NROW + r0 + q * 2 + lh;
        g_u[ip]  = __float2half(expf(t));
        g_v[ip]  = __float2half(expf(0.2f * t));
        g_th[ip] = __float2half(t);
        g_E2[i] = __float2half2_rn(expf(0.8f * c));
        g_nc[i] = __float2half2_rn(-c);
    }
}

// ---------------- K4: split-K(4), 1 warp per 16-row m-tile, N=72, 3-stage cp.async ring ----------------
__global__ __launch_bounds__(128, 5) void k4_main() {
    __shared__ __align__(16) __half  Hs[3][KC][HS_STRIDE];
    __shared__ __align__(16) __half2 U2s[3][KC/2];
    __shared__ __align__(16) __half2 V2s[3][KC/2];
    __shared__ __align__(16) __half2 T2s[3][KC/2];

    int head = blockIdx.y;
    int n0 = blockIdx.x * RT;
    int z = blockIdx.z;                  // k-split index
    int kb0 = z * ITER_PER;
    int tid = threadIdx.x;
    int lane = tid & 31, wid = tid >> 5; // wid = m-tile 0..3
    int g = lane >> 2, tc = lane & 3;

    int ra = n0 + wid * 16 + g;
    int rb = ra + 8;
    int ia = head * NROW + ra, ib = head * NROW + rb;
    __half2 Ea = g_E2[ia], nca = g_nc[ia];
    __half2 Eb = g_E2[ib], ncb = g_nc[ib];
    const uint2* adjA = (const uint2*)&g_adjbits[ra * NW];  // [kb] -> 64 cols
    const uint2* adjB = (const uint2*)&g_adjbits[rb * NW];

    float acc[9][4];
    #pragma unroll
    for (int b = 0; b < 9; b++)
        #pragma unroll
        for (int c = 0; c < 4; c++) acc[b][c] = 0.0f;

    const float4* hv4 = (const float4*)&g_hv[head * NROW * NC];
    const __half* gu = g_u + head * NROW;
    const __half* gv = g_v + head * NROW;
    const __half* gt = g_th + head * NROW;

    int kbEnd = kb0 + ITER_PER;
    auto issue = [&](int kbg, int s) {
        if (kbg < kbEnd) {
            int m0 = kbg * KC;
            #pragma unroll
            for (int i = 0; i < 5; i++) {
                int idx = tid + i * 128;
                if (idx < 64 * 9) {
                    int r = idx / 9, cg = idx - r * 9;
                    cp16(((char*)&Hs[s][r][0]) + cg * 16, (const char*)(hv4 + (m0 + r) * 10 + cg));
                }
            }
            if (tid < 24) {
                int a = tid >> 3, i = tid & 7;
                const __half* src = (a == 0 ? gu : (a == 1 ? gv : gt)) + m0 + i * 8;
                __half2* dst = (a == 0 ? &U2s[s][0] : (a == 1 ? &V2s[s][0] : &T2s[s][0])) + i * 4;
                cp16(dst, src);
            }
        }
        cp_commit();   // commit unconditionally to keep group accounting aligned
    };

    issue(kb0, 0);
    issue(kb0 + 1, 1);
    uint2 awa = __ldg(&adjA[kb0]);
    uint2 awb = __ldg(&adjB[kb0]);

    for (int k2 = 0; k2 < ITER_PER; k2++) {
        int s = k2 % 3;
        cp_wait1();            // stage k2 arrived (stage k2+1 may still be in flight)
        __syncthreads();       // all warps past compute of k2-1 -> stage (k2+2)%3 free
        issue(kb0 + k2 + 2, (k2 + 2) % 3);
        uint2 nwa = make_uint2(0u, 0u), nwb = make_uint2(0u, 0u);
        if (k2 + 1 < ITER_PER) {
            nwa = __ldg(&adjA[kb0 + k2 + 1]);
            nwb = __ldg(&adjB[kb0 + k2 + 1]);
        }

        const char* HsB = (const char*)&Hs[s][0][0];
        int qb = tc * 8;      // permuted base for this thread's column pairs
        #pragma unroll
        for (int kk = 0; kk < 4; kk++) {
            int p0 = kk * 8 + tc;            // logical pair index (for adjacency bits)
            int p1 = p0 + 4;
            uint32_t wa = (kk < 2) ? awa.x : awa.y;
            uint32_t wb = (kk < 2) ? awb.x : awb.y;
            int sh0 = (2 * p0) & 31;
            int sh1 = (2 * p1) & 31;

            // permuted smem: pairs (p0, p1) adjacent -> single 64-bit LDS each
            float2 uf = *(const float2*)&U2s[s][qb + 2 * kk];
            float2 vf = *(const float2*)&V2s[s][qb + 2 * kk];
            float2 tf = *(const float2*)&T2s[s][qb + 2 * kk];
            __half2 u0 = ((const __half2*)&uf)[0], u1 = ((const __half2*)&uf)[1];
            __half2 v0 = ((const __half2*)&vf)[0], v1 = ((const __half2*)&vf)[1];
            __half2 t0 = ((const __half2*)&tf)[0], t1 = ((const __half2*)&tf)[1];

            uint32_t a[4];
            a[0] = pval(u0, v0, t0, Ea, nca, wa, sh0);
            a[1] = pval(u0, v0, t0, Eb, ncb, wb, sh0);
            a[2] = pval(u1, v1, t1, Ea, nca, wa, sh1);
            a[3] = pval(u1, v1, t1, Eb, ncb, wb, sh1);

            const char* rowK = HsB + (kk * 16 + (lane & 15)) * (HS_STRIDE * 2);
            const char* rowB = rowK + ((lane >> 4) * 8) * 2;
            // cols 0..63: 4 x4 transposed loads, mma immediately
            #pragma unroll
            for (int gg = 0; gg < 4; gg++) {
                uint32_t b0[2], b1[2];
                ldm_x4_t(b0[0], b0[1], b1[0], b1[1],
                         smem_u32(rowB + (gg * 16) * 2));
                mma16816(&acc[2 * gg][0], a, b0);
                mma16816(&acc[2 * gg + 1][0], a, b1);
            }
            // cols 64..71 (denominator col 64 + zero pad): one x2 load
            {
                uint32_t b2[2];
                ldm_x2_t(b2[0], b2[1], smem_u32(rowK + 64 * 2));
                mma16816(&acc[8][0], a, b2);
            }
        }
        awa = nwa;
        awb = nwb;
    }

    // store unnormalized partials (cols 0..71 incl. denominator col 64)
    float* pb = g_part + ((size_t)(z * NH + head) * NROW) * 80;
    int row0 = n0 + wid * 16 + g;
    #pragma unroll
    for (int nt = 0; nt < 9; nt++) {
        int col = nt * 8 + 2 * tc;
        *(float2*)&pb[(size_t)row0 * 80 + col] = make_float2(acc[nt][0], acc[nt][1]);
        *(float2*)&pb[(size_t)(row0 + 8) * 80 + col] = make_float2(acc[nt][2], acc[nt][3]);
    }
}

// ---------------- K5: combine split-K partials + normalize + write out ----------------
__global__ __launch_bounds__(256) void k5_combine(float* __restrict__ out) {
    int head = blockIdx.y;
    int r = blockIdx.x * 64 + (threadIdx.x >> 2);
    int q = threadIdx.x & 3;
    const float* p0 = g_part + ((size_t)(0 * NH + head) * NROW + r) * 80;
    const float* p1 = g_part + ((size_t)(1 * NH + head) * NROW + r) * 80;
    const float* p2 = g_part + ((size_t)(2 * NH + head) * NROW + r) * 80;
    const float* p3 = g_part + ((size_t)(3 * NH + head) * NROW + r) * 80;
    float inv = 1.0f / (p0[64] + p1[64] + p2[64] + p3[64]);
    #pragma unroll
    for (int j = 0; j < 4; j++) {
        float4 a = *(const float4*)&p0[q * 16 + j * 4];
        float4 b = *(const float4*)&p1[q * 16 + j * 4];
        float4 c = *(const float4*)&p2[q * 16 + j * 4];
        float4 d = *(const float4*)&p3[q * 16 + j * 4];
        float4 o;
        o.x = (a.x + b.x + c.x + d.x) * inv;
        o.y = (a.y + b.y + c.y + d.y) * inv;
        o.z = (a.z + b.z + c.z + d.z) * inv;
        o.w = (a.w + b.w + c.w + d.w) * inv;
        *(float4*)&out[(size_t)r * (NH * OD) + head * OD + q * 16 + j * 4] = o;
    }
}

// ---------------- launch ----------------
extern "C" void kernel_launch(void* const* d_in, const int* in_sizes, int n_in,
                              void* d_out, int out_size) {
    const float* x       = (const float*)d_in[0];
    const float* adj     = (const float*)d_in[1];
    const float* W       = (const float*)d_in[2];
    const float* a_self  = (const float*)d_in[3];
    const float* a_neigh = (const float*)d_in[4];
    float* out = (float*)d_out;

    kA        <<<256 + NROW, 256>>>(x, adj, W, a_self, a_neigh);
    k4_main   <<<dim3(NROW / RT, NH, KSPLIT), 128>>>();
    k5_combine<<<dim3(NROW / 64, NH), 256>>>(out);
}